// round 1
// baseline (speedup 1.0000x reference)
#include <cuda_runtime.h>
#include <math.h>

#define BATCH   1024
#define D_MODEL 4096
#define D_STATE 16
#define DT_RANK 256
#define XP_COLS (DT_RANK + 2 * D_STATE)   // 288

// Scratch (allocation-free rule: __device__ globals)
__device__ float g_xp[BATCH * XP_COLS];      // 1.2 MB
__device__ float g_delta[BATCH * D_MODEL];   // 16 MB
__device__ float g_ypre[BATCH * D_MODEL];    // 16 MB

__device__ __forceinline__ float softplusf(float z) {
    return (z > 20.0f) ? z : log1pf(__expf(z));
}

__global__ void zero_xp_kernel() {
    int i = blockIdx.x * blockDim.x + threadIdx.x;
    if (i < BATCH * XP_COLS) g_xp[i] = 0.0f;
}

// ---------------------------------------------------------------------------
// Small guarded GEMM with split-K (for the 1024x288 projection; K split over
// gridDim.z, accumulated with atomicAdd). C[m,n] = sum_k A[m,k]*B[n,k].
// ---------------------------------------------------------------------------
template<int BM, int BN, int BK, int TM, int TN>
__global__ void __launch_bounds__(256)
gemm_nt_small(const float* __restrict__ A, int lda,
              const float* __restrict__ B, int ldb,
              float* __restrict__ C, int ldc,
              int M, int N, int K)
{
    __shared__ float As[BK][BM];
    __shared__ float Bs[BK][BN];
    const int tid = threadIdx.x;
    const int bm = blockIdx.y * BM;
    const int bn = blockIdx.x * BN;
    const int kchunk = K / gridDim.z;
    const int k0base = blockIdx.z * kchunk;

    // A tile: BM x BK = 64*16 = 1024 floats, 256 thr -> 1 float4 each
    const int arow = tid >> 2;            // 0..63
    const int acol = (tid & 3) << 2;      // 0,4,8,12
    // B tile: BN x BK = 32*16 = 512 floats, 256 thr -> 1 float2 each
    const int brow = tid >> 3;            // 0..31
    const int bcol = (tid & 7) << 1;      // 0..14 step 2

    const bool avalid = (bm + arow) < M;
    const bool bvalid = (bn + brow) < N;

    const float* Ap = A + (size_t)(bm + arow) * lda + acol;
    const float* Bp = B + (size_t)(bn + brow) * ldb + bcol;

    float acc[TM][TN];
    #pragma unroll
    for (int i = 0; i < TM; i++)
        #pragma unroll
        for (int j = 0; j < TN; j++) acc[i][j] = 0.0f;

    const int tx = tid & 15;   // col group (TN=2 -> 32 cols)
    const int ty = tid >> 4;   // row group (TM=4 -> 64 rows)

    for (int k0 = k0base; k0 < k0base + kchunk; k0 += BK) {
        float4 av = avalid ? *(const float4*)(Ap + k0) : make_float4(0, 0, 0, 0);
        float2 bv = bvalid ? *(const float2*)(Bp + k0) : make_float2(0, 0);
        As[acol + 0][arow] = av.x;
        As[acol + 1][arow] = av.y;
        As[acol + 2][arow] = av.z;
        As[acol + 3][arow] = av.w;
        Bs[bcol + 0][brow] = bv.x;
        Bs[bcol + 1][brow] = bv.y;
        __syncthreads();
        #pragma unroll
        for (int kk = 0; kk < BK; kk++) {
            float ra[TM], rb[TN];
            #pragma unroll
            for (int i = 0; i < TM; i++) ra[i] = As[kk][ty * TM + i];
            #pragma unroll
            for (int j = 0; j < TN; j++) rb[j] = Bs[kk][tx * TN + j];
            #pragma unroll
            for (int i = 0; i < TM; i++)
                #pragma unroll
                for (int j = 0; j < TN; j++) acc[i][j] += ra[i] * rb[j];
        }
        __syncthreads();
    }

    #pragma unroll
    for (int i = 0; i < TM; i++) {
        int row = bm + ty * TM + i;
        if (row >= M) continue;
        #pragma unroll
        for (int j = 0; j < TN; j++) {
            int col = bn + tx * TN + j;
            if (col < N) atomicAdd(&C[(size_t)row * ldc + col], acc[i][j]);
        }
    }
}

// ---------------------------------------------------------------------------
// Main SGEMM: 128x128 tile, BK=8, 8x8 per thread, 256 threads.
// C[m,n] = sum_k A[m,k]*B[n,k].  MODE 1: store softplus(acc + bias[n]).
// Requires M % 128 == 0, K % 8 == 0. N guarded.
// ---------------------------------------------------------------------------
template<int MODE>
__global__ void __launch_bounds__(256)
gemm_nt_128(const float* __restrict__ A, int lda,
            const float* __restrict__ B, int ldb,
            float* __restrict__ C, int ldc,
            int N, int K,
            const float* __restrict__ bias)
{
    constexpr int BM = 128, BN = 128, BK = 8;
    __shared__ float As[BK][BM];
    __shared__ float Bs[BK][BN];
    const int tid = threadIdx.x;
    const int bm = blockIdx.y * BM;
    const int bn = blockIdx.x * BN;

    // Tile loads: 128x8 = 1024 floats each, 1 float4 per thread
    const int lrow = tid >> 1;          // 0..127
    const int lcol = (tid & 1) << 2;    // 0 or 4

    const float* Ap = A + (size_t)(bm + lrow) * lda + lcol;
    const bool bvalid = (bn + lrow) < N;
    const float* Bp = B + (size_t)(bn + lrow) * ldb + lcol;

    float acc[8][8];
    #pragma unroll
    for (int i = 0; i < 8; i++)
        #pragma unroll
        for (int j = 0; j < 8; j++) acc[i][j] = 0.0f;

    const int tx = tid & 15;   // col group of 8
    const int ty = tid >> 4;   // row group of 8

    for (int k0 = 0; k0 < K; k0 += BK) {
        float4 av = *(const float4*)(Ap + k0);
        float4 bv = bvalid ? *(const float4*)(Bp + k0) : make_float4(0, 0, 0, 0);
        As[lcol + 0][lrow] = av.x;
        As[lcol + 1][lrow] = av.y;
        As[lcol + 2][lrow] = av.z;
        As[lcol + 3][lrow] = av.w;
        Bs[lcol + 0][lrow] = bv.x;
        Bs[lcol + 1][lrow] = bv.y;
        Bs[lcol + 2][lrow] = bv.z;
        Bs[lcol + 3][lrow] = bv.w;
        __syncthreads();
        #pragma unroll
        for (int kk = 0; kk < BK; kk++) {
            float ra[8], rb[8];
            *(float4*)(ra)     = *(const float4*)&As[kk][ty * 8];
            *(float4*)(ra + 4) = *(const float4*)&As[kk][ty * 8 + 4];
            *(float4*)(rb)     = *(const float4*)&Bs[kk][tx * 8];
            *(float4*)(rb + 4) = *(const float4*)&Bs[kk][tx * 8 + 4];
            #pragma unroll
            for (int i = 0; i < 8; i++)
                #pragma unroll
                for (int j = 0; j < 8; j++) acc[i][j] += ra[i] * rb[j];
        }
        __syncthreads();
    }

    #pragma unroll
    for (int i = 0; i < 8; i++) {
        int row = bm + ty * 8 + i;
        #pragma unroll
        for (int j = 0; j < 8; j++) {
            int col = bn + tx * 8 + j;
            if (col < N) {
                float v = acc[i][j];
                if (MODE == 1) v = softplusf(v + bias[col]);
                C[(size_t)row * ldc + col] = v;
            }
        }
    }
}

// ---------------------------------------------------------------------------
// Fused state update:
//   h_new[b,d,n] = exp(delta[b,d]*A[n]) * h[b,d,n] + delta[b,d]*B[b,n]*x[b,d]
//   ypre[b,d]    = sum_n C[b,n]*h_new[b,d,n] + D[d]*x[b,d]
// B = g_xp[b, 256:272], C = g_xp[b, 272:288].  HBM-bound (~560 MB).
// ---------------------------------------------------------------------------
__global__ void __launch_bounds__(256)
state_update(const float* __restrict__ x,
             const float* __restrict__ h,
             const float* __restrict__ A_log,
             const float* __restrict__ Dv,
             float* __restrict__ h_new,
             float* __restrict__ ypre)
{
    __shared__ float sA[D_STATE], sB[D_STATE], sC[D_STATE];
    const int b = blockIdx.y;
    const int d = blockIdx.x * blockDim.x + threadIdx.x;

    if (threadIdx.x < D_STATE) {
        int n = threadIdx.x;
        sA[n] = -expf(A_log[n]);
        sB[n] = g_xp[(size_t)b * XP_COLS + DT_RANK + n];
        sC[n] = g_xp[(size_t)b * XP_COLS + DT_RANK + D_STATE + n];
    }
    __syncthreads();

    const size_t bd = (size_t)b * D_MODEL + d;
    const float delta = g_delta[bd];
    const float xv = x[bd];
    const float dx = delta * xv;

    const float4* hp = (const float4*)(h + bd * D_STATE);
    float4* hop = (float4*)(h_new + bd * D_STATE);

    float acc = 0.0f;
    #pragma unroll
    for (int q = 0; q < 4; q++) {
        float4 hv = hp[q];
        float h0 = __expf(delta * sA[4 * q + 0]) * hv.x + dx * sB[4 * q + 0];
        float h1 = __expf(delta * sA[4 * q + 1]) * hv.y + dx * sB[4 * q + 1];
        float h2 = __expf(delta * sA[4 * q + 2]) * hv.z + dx * sB[4 * q + 2];
        float h3 = __expf(delta * sA[4 * q + 3]) * hv.w + dx * sB[4 * q + 3];
        acc += sC[4 * q + 0] * h0 + sC[4 * q + 1] * h1
             + sC[4 * q + 2] * h2 + sC[4 * q + 3] * h3;
        hop[q] = make_float4(h0, h1, h2, h3);
    }
    ypre[bd] = acc + Dv[d] * xv;
}

// ---------------------------------------------------------------------------
// Launch. Inputs (metadata order): x, h, W_xproj, W_dt, b_dt, A_log, D, W_out.
// Output: [y (1024*4096), h_new (1024*4096*16)].
// ---------------------------------------------------------------------------
extern "C" void kernel_launch(void* const* d_in, const int* in_sizes, int n_in,
                              void* d_out, int out_size)
{
    const float* x    = (const float*)d_in[0];
    const float* h    = (const float*)d_in[1];
    const float* Wxp  = (const float*)d_in[2];
    const float* Wdt  = (const float*)d_in[3];
    const float* bdt  = (const float*)d_in[4];
    const float* Alog = (const float*)d_in[5];
    const float* Dv   = (const float*)d_in[6];
    const float* Wout = (const float*)d_in[7];

    float* y_out    = (float*)d_out;
    float* hnew_out = y_out + (size_t)BATCH * D_MODEL;

    float *xp_p = nullptr, *delta_p = nullptr, *ypre_p = nullptr;
    cudaGetSymbolAddress((void**)&xp_p, g_xp);
    cudaGetSymbolAddress((void**)&delta_p, g_delta);
    cudaGetSymbolAddress((void**)&ypre_p, g_ypre);

    // G1: xp = x @ W_xproj^T  (1024x288, K=4096) with split-K=4 (576 blocks)
    zero_xp_kernel<<<(BATCH * XP_COLS + 255) / 256, 256>>>();
    gemm_nt_small<64, 32, 16, 4, 2><<<dim3((XP_COLS + 31) / 32, BATCH / 64, 4), 256>>>(
        x, D_MODEL, Wxp, D_MODEL, xp_p, XP_COLS, BATCH, XP_COLS, D_MODEL);

    // G2: delta = softplus(xp[:, :256] @ W_dt^T + b_dt)  (1024x4096, K=256)
    gemm_nt_128<1><<<dim3(D_MODEL / 128, BATCH / 128), 256>>>(
        xp_p, XP_COLS, Wdt, DT_RANK, delta_p, D_MODEL, D_MODEL, DT_RANK, bdt);

    // S: state update + ypre (HBM-bound)
    state_update<<<dim3(D_MODEL / 256, BATCH), 256>>>(
        x, h, Alog, Dv, hnew_out, ypre_p);

    // G3: y = ypre @ W_out^T  (1024x4096, K=4096) — dominant cost this round
    gemm_nt_128<0><<<dim3(D_MODEL / 128, BATCH / 128), 256>>>(
        ypre_p, D_MODEL, Wout, D_MODEL, y_out, D_MODEL, D_MODEL, D_MODEL, nullptr);
}

// round 4
// speedup vs baseline: 1.8348x; 1.8348x over previous
#include <cuda_runtime.h>
#include <cuda_bf16.h>
#include <math.h>
#include <stdint.h>

#define BATCH   1024
#define D_MODEL 4096
#define D_STATE 16
#define DT_RANK 256
#define XP_COLS (DT_RANK + 2 * D_STATE)   // 288

// ---------------- scratch (allocation-free rule: __device__ globals) --------
__device__ float g_xp[BATCH * XP_COLS];
__device__ float g_delta[BATCH * D_MODEL];
__device__ __nv_bfloat16 g_Whi[(size_t)D_MODEL * D_MODEL];
__device__ __nv_bfloat16 g_Wlo[(size_t)D_MODEL * D_MODEL];
__device__ __nv_bfloat16 g_Yhi[(size_t)BATCH * D_MODEL];
__device__ __nv_bfloat16 g_Ylo[(size_t)BATCH * D_MODEL];

__device__ __forceinline__ float softplusf(float z) {
    return (z > 20.0f) ? z : log1pf(__expf(z));
}

// ---------------- PTX helpers (sm_80-class only; no 'a'-target features) ----
__device__ __forceinline__ uint32_t smem_u32(const void* p) {
    uint32_t a;
    asm("{ .reg .u64 t; cvta.to.shared.u64 t, %1; cvt.u32.u64 %0, t; }" : "=r"(a) : "l"(p));
    return a;
}
__device__ __forceinline__ void cpasync16(uint32_t dst, const void* src) {
    asm volatile("cp.async.cg.shared.global [%0], [%1], 16;" :: "r"(dst), "l"(src));
}
__device__ __forceinline__ void cpasync_commit() {
    asm volatile("cp.async.commit_group;" ::: "memory");
}
__device__ __forceinline__ void ldmatrix_x4(uint32_t* r, uint32_t addr) {
    asm volatile("ldmatrix.sync.aligned.m8n8.x4.shared.b16 {%0,%1,%2,%3}, [%4];"
                 : "=r"(r[0]), "=r"(r[1]), "=r"(r[2]), "=r"(r[3]) : "r"(addr));
}
__device__ __forceinline__ void mma_bf16(float* c, const uint32_t* a, const uint32_t* b) {
    asm volatile(
        "mma.sync.aligned.m16n8k16.row.col.f32.bf16.bf16.f32 "
        "{%0,%1,%2,%3}, {%4,%5,%6,%7}, {%8,%9}, {%0,%1,%2,%3};"
        : "+f"(c[0]), "+f"(c[1]), "+f"(c[2]), "+f"(c[3])
        : "r"(a[0]), "r"(a[1]), "r"(a[2]), "r"(a[3]), "r"(b[0]), "r"(b[1]));
}

// ---------------------------------------------------------------------------
// Misc small kernels
// ---------------------------------------------------------------------------
__global__ void zero_xp_kernel() {
    int i = blockIdx.x * blockDim.x + threadIdx.x;
    if (i < BATCH * XP_COLS) g_xp[i] = 0.0f;
}

// Split W_out (fp32) into bf16 hi/lo. 16M elems, float4 per thread.
__global__ void __launch_bounds__(256) split_w_kernel(const float* __restrict__ in) {
    size_t i = ((size_t)blockIdx.x * blockDim.x + threadIdx.x) * 4;
    float4 v = *(const float4*)(in + i);
    __nv_bfloat16 h0 = __float2bfloat16(v.x);
    __nv_bfloat16 h1 = __float2bfloat16(v.y);
    __nv_bfloat16 h2 = __float2bfloat16(v.z);
    __nv_bfloat16 h3 = __float2bfloat16(v.w);
    __nv_bfloat16 l0 = __float2bfloat16(v.x - __bfloat162float(h0));
    __nv_bfloat16 l1 = __float2bfloat16(v.y - __bfloat162float(h1));
    __nv_bfloat16 l2 = __float2bfloat16(v.z - __bfloat162float(h2));
    __nv_bfloat16 l3 = __float2bfloat16(v.w - __bfloat162float(h3));
    __nv_bfloat162* hp = (__nv_bfloat162*)(g_Whi + i);
    __nv_bfloat162* lp = (__nv_bfloat162*)(g_Wlo + i);
    hp[0] = __nv_bfloat162(h0, h1); hp[1] = __nv_bfloat162(h2, h3);
    lp[0] = __nv_bfloat162(l0, l1); lp[1] = __nv_bfloat162(l2, l3);
}

// ---------------------------------------------------------------------------
// Small guarded GEMM with split-K (G1). C[m,n] = sum_k A[m,k]*B[n,k].
// ---------------------------------------------------------------------------
template<int BM, int BN, int BK, int TM, int TN>
__global__ void __launch_bounds__(256)
gemm_nt_small(const float* __restrict__ A, int lda,
              const float* __restrict__ B, int ldb,
              float* __restrict__ C, int ldc,
              int M, int N, int K)
{
    __shared__ float As[BK][BM];
    __shared__ float Bs[BK][BN];
    const int tid = threadIdx.x;
    const int bm = blockIdx.y * BM;
    const int bn = blockIdx.x * BN;
    const int kchunk = K / gridDim.z;
    const int k0base = blockIdx.z * kchunk;

    const int arow = tid >> 2;
    const int acol = (tid & 3) << 2;
    const int brow = tid >> 3;
    const int bcol = (tid & 7) << 1;

    const bool avalid = (bm + arow) < M;
    const bool bvalid = (bn + brow) < N;

    const float* Ap = A + (size_t)(bm + arow) * lda + acol;
    const float* Bp = B + (size_t)(bn + brow) * ldb + bcol;

    float acc[TM][TN];
    #pragma unroll
    for (int i = 0; i < TM; i++)
        #pragma unroll
        for (int j = 0; j < TN; j++) acc[i][j] = 0.0f;

    const int tx = tid & 15;
    const int ty = tid >> 4;

    for (int k0 = k0base; k0 < k0base + kchunk; k0 += BK) {
        float4 av = avalid ? *(const float4*)(Ap + k0) : make_float4(0, 0, 0, 0);
        float2 bv = bvalid ? *(const float2*)(Bp + k0) : make_float2(0, 0);
        As[acol + 0][arow] = av.x;
        As[acol + 1][arow] = av.y;
        As[acol + 2][arow] = av.z;
        As[acol + 3][arow] = av.w;
        Bs[bcol + 0][brow] = bv.x;
        Bs[bcol + 1][brow] = bv.y;
        __syncthreads();
        #pragma unroll
        for (int kk = 0; kk < BK; kk++) {
            float ra[TM], rb[TN];
            #pragma unroll
            for (int i = 0; i < TM; i++) ra[i] = As[kk][ty * TM + i];
            #pragma unroll
            for (int j = 0; j < TN; j++) rb[j] = Bs[kk][tx * TN + j];
            #pragma unroll
            for (int i = 0; i < TM; i++)
                #pragma unroll
                for (int j = 0; j < TN; j++) acc[i][j] += ra[i] * rb[j];
        }
        __syncthreads();
    }

    #pragma unroll
    for (int i = 0; i < TM; i++) {
        int row = bm + ty * TM + i;
        if (row >= M) continue;
        #pragma unroll
        for (int j = 0; j < TN; j++) {
            int col = bn + tx * TN + j;
            if (col < N) atomicAdd(&C[(size_t)row * ldc + col], acc[i][j]);
        }
    }
}

// ---------------------------------------------------------------------------
// fp32 SGEMM 128x128 (G2). MODE 1: softplus(acc + bias[n]).
// ---------------------------------------------------------------------------
template<int MODE>
__global__ void __launch_bounds__(256)
gemm_nt_128(const float* __restrict__ A, int lda,
            const float* __restrict__ B, int ldb,
            float* __restrict__ C, int ldc,
            int N, int K,
            const float* __restrict__ bias)
{
    constexpr int BM = 128, BN = 128, BK = 8;
    __shared__ float As[BK][BM];
    __shared__ float Bs[BK][BN];
    const int tid = threadIdx.x;
    const int bm = blockIdx.y * BM;
    const int bn = blockIdx.x * BN;

    const int lrow = tid >> 1;
    const int lcol = (tid & 1) << 2;

    const float* Ap = A + (size_t)(bm + lrow) * lda + lcol;
    const bool bvalid = (bn + lrow) < N;
    const float* Bp = B + (size_t)(bn + lrow) * ldb + lcol;

    float acc[8][8];
    #pragma unroll
    for (int i = 0; i < 8; i++)
        #pragma unroll
        for (int j = 0; j < 8; j++) acc[i][j] = 0.0f;

    const int tx = tid & 15;
    const int ty = tid >> 4;

    for (int k0 = 0; k0 < K; k0 += BK) {
        float4 av = *(const float4*)(Ap + k0);
        float4 bv = bvalid ? *(const float4*)(Bp + k0) : make_float4(0, 0, 0, 0);
        As[lcol + 0][lrow] = av.x;
        As[lcol + 1][lrow] = av.y;
        As[lcol + 2][lrow] = av.z;
        As[lcol + 3][lrow] = av.w;
        Bs[lcol + 0][lrow] = bv.x;
        Bs[lcol + 1][lrow] = bv.y;
        Bs[lcol + 2][lrow] = bv.z;
        Bs[lcol + 3][lrow] = bv.w;
        __syncthreads();
        #pragma unroll
        for (int kk = 0; kk < BK; kk++) {
            float ra[8], rb[8];
            *(float4*)(ra)     = *(const float4*)&As[kk][ty * 8];
            *(float4*)(ra + 4) = *(const float4*)&As[kk][ty * 8 + 4];
            *(float4*)(rb)     = *(const float4*)&Bs[kk][tx * 8];
            *(float4*)(rb + 4) = *(const float4*)&Bs[kk][tx * 8 + 4];
            #pragma unroll
            for (int i = 0; i < 8; i++)
                #pragma unroll
                for (int j = 0; j < 8; j++) acc[i][j] += ra[i] * rb[j];
        }
        __syncthreads();
    }

    #pragma unroll
    for (int i = 0; i < 8; i++) {
        int row = bm + ty * 8 + i;
        #pragma unroll
        for (int j = 0; j < 8; j++) {
            int col = bn + tx * 8 + j;
            if (col < N) {
                float v = acc[i][j];
                if (MODE == 1) v = softplusf(v + bias[col]);
                C[(size_t)row * ldc + col] = v;
            }
        }
    }
}

// ---------------------------------------------------------------------------
// Fused state update. Writes h_new and ypre split directly to bf16 hi/lo.
// ---------------------------------------------------------------------------
__global__ void __launch_bounds__(256)
state_update(const float* __restrict__ x,
             const float* __restrict__ h,
             const float* __restrict__ A_log,
             const float* __restrict__ Dv,
             float* __restrict__ h_new)
{
    __shared__ float sA[D_STATE], sB[D_STATE], sC[D_STATE];
    const int b = blockIdx.y;
    const int d = blockIdx.x * blockDim.x + threadIdx.x;

    if (threadIdx.x < D_STATE) {
        int n = threadIdx.x;
        sA[n] = -expf(A_log[n]);
        sB[n] = g_xp[(size_t)b * XP_COLS + DT_RANK + n];
        sC[n] = g_xp[(size_t)b * XP_COLS + DT_RANK + D_STATE + n];
    }
    __syncthreads();

    const size_t bd = (size_t)b * D_MODEL + d;
    const float delta = g_delta[bd];
    const float xv = x[bd];
    const float dx = delta * xv;

    const float4* hp = (const float4*)(h + bd * D_STATE);
    float4* hop = (float4*)(h_new + bd * D_STATE);

    float acc = 0.0f;
    #pragma unroll
    for (int q = 0; q < 4; q++) {
        float4 hv = hp[q];
        float h0 = __expf(delta * sA[4 * q + 0]) * hv.x + dx * sB[4 * q + 0];
        float h1 = __expf(delta * sA[4 * q + 1]) * hv.y + dx * sB[4 * q + 1];
        float h2 = __expf(delta * sA[4 * q + 2]) * hv.z + dx * sB[4 * q + 2];
        float h3 = __expf(delta * sA[4 * q + 3]) * hv.w + dx * sB[4 * q + 3];
        acc += sC[4 * q + 0] * h0 + sC[4 * q + 1] * h1
             + sC[4 * q + 2] * h2 + sC[4 * q + 3] * h3;
        hop[q] = make_float4(h0, h1, h2, h3);
    }
    float ypre = acc + Dv[d] * xv;
    __nv_bfloat16 hi = __float2bfloat16(ypre);
    __nv_bfloat16 lo = __float2bfloat16(ypre - __bfloat162float(hi));
    g_Yhi[bd] = hi;
    g_Ylo[bd] = lo;
}

// ---------------------------------------------------------------------------
// G3 via mma.sync (HMMA): C[1024,4096] = Y @ W^T, bf16x3 split.
// CTA 128x128, BK=32 halfs, 8 warps (2M x 4N), warp tile 64x32.
// SMEM rows padded to 80B. Double buffered cp.async.
// ---------------------------------------------------------------------------
#define HB_BM 128
#define HB_BN 128
#define HB_BK 32
#define HB_NIT (D_MODEL / HB_BK)      // 128
#define ROW_B 80                      // 64B data + 16B pad
#define TILE_B (128 * ROW_B)          // 10240
#define OFF_AHI 0
#define OFF_ALO (1 * TILE_B)
#define OFF_BHI (2 * TILE_B)
#define OFF_BLO (3 * TILE_B)
#define STAGE_B (4 * TILE_B)          // 40960
#define HB_SMEM (2 * STAGE_B)         // 81920

__global__ void __launch_bounds__(256, 1)
gemm_hmma(const __nv_bfloat16* __restrict__ Ahi, const __nv_bfloat16* __restrict__ Alo,
          const __nv_bfloat16* __restrict__ Bhi, const __nv_bfloat16* __restrict__ Blo,
          float* __restrict__ C)
{
    extern __shared__ char smem[];
    const uint32_t sb = smem_u32(smem);
    const int tid = threadIdx.x;
    const int wid = tid >> 5;
    const int lane = tid & 31;
    const int warp_m = wid >> 2;          // 0-1, 64 rows each
    const int warp_n = wid & 3;           // 0-3, 32 cols each
    const int bm = blockIdx.x * HB_BM;
    const int bn = blockIdx.y * HB_BN;

    // Stage fill: each tile = 128 rows x 4 chunks of 16B = 512 chunks.
    // 256 threads x 2 iterations, fully coalesced (consecutive tid -> consecutive 16B).
    auto load_stage = [&](uint32_t st, int k0) {
        #pragma unroll
        for (int cc = 0; cc < 2; cc++) {
            const int idx = tid + 256 * cc;
            const int row = idx >> 2;
            const int ch  = idx & 3;
            const uint32_t d = st + (uint32_t)(row * ROW_B + ch * 16);
            const int gk = k0 + ch * 8;
            cpasync16(d + OFF_AHI, Ahi + (size_t)(bm + row) * D_MODEL + gk);
            cpasync16(d + OFF_ALO, Alo + (size_t)(bm + row) * D_MODEL + gk);
            cpasync16(d + OFF_BHI, Bhi + (size_t)(bn + row) * D_MODEL + gk);
            cpasync16(d + OFF_BLO, Blo + (size_t)(bn + row) * D_MODEL + gk);
        }
        cpasync_commit();
    };

    // ldmatrix per-lane byte offsets (within a tile, ks=0)
    uint32_t aoff[4], boff[2];
    #pragma unroll
    for (int mi = 0; mi < 4; mi++)
        aoff[mi] = (uint32_t)((warp_m * 64 + mi * 16 + (lane & 15)) * ROW_B + (lane >> 4) * 16);
    #pragma unroll
    for (int pi = 0; pi < 2; pi++) {
        int chunk = lane >> 3;
        int n = warp_n * 32 + pi * 16 + (chunk >> 1) * 8 + (lane & 7);
        boff[pi] = (uint32_t)(n * ROW_B + (chunk & 1) * 16);
    }

    float acc[4][4][4];
    #pragma unroll
    for (int mi = 0; mi < 4; mi++)
        #pragma unroll
        for (int ni = 0; ni < 4; ni++)
            #pragma unroll
            for (int q = 0; q < 4; q++) acc[mi][ni][q] = 0.0f;

    // prologue: stage 0
    load_stage(sb, 0);

    for (int it = 0; it < HB_NIT; it++) {
        if (it + 1 < HB_NIT) {
            load_stage(sb + ((it + 1) & 1) * STAGE_B, (it + 1) * HB_BK);
            asm volatile("cp.async.wait_group 1;" ::: "memory");
        } else {
            asm volatile("cp.async.wait_group 0;" ::: "memory");
        }
        __syncthreads();

        const uint32_t st = sb + (it & 1) * STAGE_B;
        #pragma unroll
        for (int ks = 0; ks < 2; ks++) {
            uint32_t a_hi[4][4], a_lo[4][4], b_hi[2][4], b_lo[2][4];
            #pragma unroll
            for (int mi = 0; mi < 4; mi++) {
                ldmatrix_x4(a_hi[mi], st + OFF_AHI + aoff[mi] + ks * 32);
                ldmatrix_x4(a_lo[mi], st + OFF_ALO + aoff[mi] + ks * 32);
            }
            #pragma unroll
            for (int pi = 0; pi < 2; pi++) {
                ldmatrix_x4(b_hi[pi], st + OFF_BHI + boff[pi] + ks * 32);
                ldmatrix_x4(b_lo[pi], st + OFF_BLO + boff[pi] + ks * 32);
            }
            #pragma unroll
            for (int mi = 0; mi < 4; mi++) {
                #pragma unroll
                for (int ni = 0; ni < 4; ni++) {
                    const int pi = ni >> 1;
                    const int sel = (ni & 1) * 2;
                    uint32_t bh[2] = {b_hi[pi][sel], b_hi[pi][sel + 1]};
                    uint32_t bl[2] = {b_lo[pi][sel], b_lo[pi][sel + 1]};
                    mma_bf16(acc[mi][ni], a_hi[mi], bh);
                    mma_bf16(acc[mi][ni], a_lo[mi], bh);
                    mma_bf16(acc[mi][ni], a_hi[mi], bl);
                }
            }
        }
        __syncthreads();
    }

    // epilogue: fragment -> global fp32
    #pragma unroll
    for (int mi = 0; mi < 4; mi++) {
        const int row = bm + warp_m * 64 + mi * 16 + (lane >> 2);
        #pragma unroll
        for (int ni = 0; ni < 4; ni++) {
            const int col = bn + warp_n * 32 + ni * 8 + (lane & 3) * 2;
            *(float2*)(C + (size_t)row * D_MODEL + col) =
                make_float2(acc[mi][ni][0], acc[mi][ni][1]);
            *(float2*)(C + (size_t)(row + 8) * D_MODEL + col) =
                make_float2(acc[mi][ni][2], acc[mi][ni][3]);
        }
    }
}

// ---------------------------------------------------------------------------
// Launch. Inputs: x, h, W_xproj, W_dt, b_dt, A_log, D, W_out.
// Output: [y (1024*4096), h_new (1024*4096*16)].
// ---------------------------------------------------------------------------
extern "C" void kernel_launch(void* const* d_in, const int* in_sizes, int n_in,
                              void* d_out, int out_size)
{
    const float* x    = (const float*)d_in[0];
    const float* h    = (const float*)d_in[1];
    const float* Wxp  = (const float*)d_in[2];
    const float* Wdt  = (const float*)d_in[3];
    const float* bdt  = (const float*)d_in[4];
    const float* Alog = (const float*)d_in[5];
    const float* Dv   = (const float*)d_in[6];
    const float* Wout = (const float*)d_in[7];

    float* y_out    = (float*)d_out;
    float* hnew_out = y_out + (size_t)BATCH * D_MODEL;

    float *xp_p = nullptr, *delta_p = nullptr;
    __nv_bfloat16 *whi_p = nullptr, *wlo_p = nullptr, *yhi_p = nullptr, *ylo_p = nullptr;
    cudaGetSymbolAddress((void**)&xp_p, g_xp);
    cudaGetSymbolAddress((void**)&delta_p, g_delta);
    cudaGetSymbolAddress((void**)&whi_p, g_Whi);
    cudaGetSymbolAddress((void**)&wlo_p, g_Wlo);
    cudaGetSymbolAddress((void**)&yhi_p, g_Yhi);
    cudaGetSymbolAddress((void**)&ylo_p, g_Ylo);

    cudaFuncSetAttribute(gemm_hmma, cudaFuncAttributeMaxDynamicSharedMemorySize, HB_SMEM);

    // Split W_out into bf16 hi/lo
    split_w_kernel<<<(D_MODEL * D_MODEL) / (4 * 256), 256>>>(Wout);

    // G1: xp = x @ W_xproj^T  (1024x288, K=4096), split-K=4
    zero_xp_kernel<<<(BATCH * XP_COLS + 255) / 256, 256>>>();
    gemm_nt_small<64, 32, 16, 4, 2><<<dim3((XP_COLS + 31) / 32, BATCH / 64, 4), 256>>>(
        x, D_MODEL, Wxp, D_MODEL, xp_p, XP_COLS, BATCH, XP_COLS, D_MODEL);

    // G2: delta = softplus(xp[:, :256] @ W_dt^T + b_dt)
    gemm_nt_128<1><<<dim3(D_MODEL / 128, BATCH / 128), 256>>>(
        xp_p, XP_COLS, Wdt, DT_RANK, delta_p, D_MODEL, D_MODEL, DT_RANK, bdt);

    // S: state update + ypre -> bf16 hi/lo (fused split)
    state_update<<<dim3(D_MODEL / 256, BATCH), 256>>>(x, h, Alog, Dv, hnew_out);

    // G3 via mma.sync tensor cores: y = ypre @ W_out^T
    gemm_hmma<<<dim3(BATCH / HB_BM, D_MODEL / HB_BN), 256, HB_SMEM>>>(
        yhi_p, ylo_p, whi_p, wlo_p, y_out);
}

// round 5
// speedup vs baseline: 2.5456x; 1.3874x over previous
#include <cuda_runtime.h>
#include <cuda_bf16.h>
#include <cuda_fp16.h>
#include <math.h>
#include <stdint.h>

#define BATCH   1024
#define D_MODEL 4096
#define D_STATE 16
#define DT_RANK 256
#define XP_COLS (DT_RANK + 2 * D_STATE)   // 288
#define WXP_PAD 384                        // 288 padded to 3 x 128

// ---------------- scratch (allocation-free rule: __device__ globals) --------
__device__ float g_xp[BATCH * XP_COLS];
__device__ float g_delta[BATCH * D_MODEL];
__device__ uint16_t g_Wh16[(size_t)D_MODEL * D_MODEL];   // fp16(W_out)
__device__ uint16_t g_Yh[(size_t)BATCH * D_MODEL];       // fp16 hi(ypre)
__device__ uint16_t g_Yl[(size_t)BATCH * D_MODEL];       // fp16 lo(ypre)
__device__ uint16_t g_xh[(size_t)BATCH * D_MODEL];       // bf16 hi(x)
__device__ uint16_t g_xl[(size_t)BATCH * D_MODEL];       // bf16 lo(x)
__device__ uint16_t g_Wxh[(size_t)WXP_PAD * D_MODEL];    // bf16 hi(W_xproj), padded
__device__ uint16_t g_Wxl[(size_t)WXP_PAD * D_MODEL];
__device__ uint16_t g_dh[(size_t)BATCH * DT_RANK];       // bf16 hi(delta_raw)
__device__ uint16_t g_dl[(size_t)BATCH * DT_RANK];
__device__ uint16_t g_Wdh[(size_t)D_MODEL * DT_RANK];    // bf16 hi(W_dt)
__device__ uint16_t g_Wdl[(size_t)D_MODEL * DT_RANK];

__device__ __forceinline__ float softplusf(float z) {
    return (z > 20.0f) ? z : log1pf(__expf(z));
}

// ---------------- PTX helpers (sm_80-class only; no 'a'-target features) ----
__device__ __forceinline__ uint32_t smem_u32(const void* p) {
    uint32_t a;
    asm("{ .reg .u64 t; cvta.to.shared.u64 t, %1; cvt.u32.u64 %0, t; }" : "=r"(a) : "l"(p));
    return a;
}
__device__ __forceinline__ void cpasync16(uint32_t dst, const void* src) {
    asm volatile("cp.async.cg.shared.global [%0], [%1], 16;" :: "r"(dst), "l"(src));
}
__device__ __forceinline__ void cpasync_commit() {
    asm volatile("cp.async.commit_group;" ::: "memory");
}
__device__ __forceinline__ void ldmatrix_x4(uint32_t* r, uint32_t addr) {
    asm volatile("ldmatrix.sync.aligned.m8n8.x4.shared.b16 {%0,%1,%2,%3}, [%4];"
                 : "=r"(r[0]), "=r"(r[1]), "=r"(r[2]), "=r"(r[3]) : "r"(addr));
}
// DT: 0 = bf16, 1 = fp16
template<int DT>
__device__ __forceinline__ void mma16(float* c, const uint32_t* a, const uint32_t* b) {
    if constexpr (DT == 0) {
        asm volatile(
            "mma.sync.aligned.m16n8k16.row.col.f32.bf16.bf16.f32 "
            "{%0,%1,%2,%3}, {%4,%5,%6,%7}, {%8,%9}, {%0,%1,%2,%3};"
            : "+f"(c[0]), "+f"(c[1]), "+f"(c[2]), "+f"(c[3])
            : "r"(a[0]), "r"(a[1]), "r"(a[2]), "r"(a[3]), "r"(b[0]), "r"(b[1]));
    } else {
        asm volatile(
            "mma.sync.aligned.m16n8k16.row.col.f32.f16.f16.f32 "
            "{%0,%1,%2,%3}, {%4,%5,%6,%7}, {%8,%9}, {%0,%1,%2,%3};"
            : "+f"(c[0]), "+f"(c[1]), "+f"(c[2]), "+f"(c[3])
            : "r"(a[0]), "r"(a[1]), "r"(a[2]), "r"(a[3]), "r"(b[0]), "r"(b[1]));
    }
}

// ---------------------------------------------------------------------------
// Conversion / split kernels
// ---------------------------------------------------------------------------
__global__ void zero_xp_kernel() {
    int i = blockIdx.x * blockDim.x + threadIdx.x;
    if (i < BATCH * XP_COLS) g_xp[i] = 0.0f;
}

// fp32 -> bf16 hi/lo (exact grid, 4 elems/thread)
__global__ void __launch_bounds__(256)
split_bf16_k(const float* __restrict__ in, uint16_t* __restrict__ h, uint16_t* __restrict__ l) {
    size_t i = ((size_t)blockIdx.x * blockDim.x + threadIdx.x) * 4;
    float4 v = *(const float4*)(in + i);
    float vv[4] = {v.x, v.y, v.z, v.w};
    #pragma unroll
    for (int q = 0; q < 4; q++) {
        __nv_bfloat16 hi = __float2bfloat16(vv[q]);
        __nv_bfloat16 lo = __float2bfloat16(vv[q] - __bfloat162float(hi));
        h[i + q] = *(uint16_t*)&hi;
        l[i + q] = *(uint16_t*)&lo;
    }
}

// fp32 -> fp16 single (W_out)
__global__ void __launch_bounds__(256)
conv_fp16_k(const float* __restrict__ in, uint16_t* __restrict__ out) {
    size_t i = ((size_t)blockIdx.x * blockDim.x + threadIdx.x) * 4;
    float4 v = *(const float4*)(in + i);
    __half h0 = __float2half_rn(v.x), h1 = __float2half_rn(v.y);
    __half h2 = __float2half_rn(v.z), h3 = __float2half_rn(v.w);
    uint16_t* o = out + i;
    o[0] = *(uint16_t*)&h0; o[1] = *(uint16_t*)&h1;
    o[2] = *(uint16_t*)&h2; o[3] = *(uint16_t*)&h3;
}

// W_xproj (288x4096) -> bf16 hi/lo padded to 384 rows (zeros beyond 288)
__global__ void __launch_bounds__(256)
split_wxproj_k(const float* __restrict__ in) {
    size_t i = ((size_t)blockIdx.x * blockDim.x + threadIdx.x) * 4;   // over 384*4096
    int row = (int)(i >> 12);
    float vv[4] = {0.f, 0.f, 0.f, 0.f};
    if (row < XP_COLS) {
        float4 v = *(const float4*)(in + i);
        vv[0] = v.x; vv[1] = v.y; vv[2] = v.z; vv[3] = v.w;
    }
    #pragma unroll
    for (int q = 0; q < 4; q++) {
        __nv_bfloat16 hi = __float2bfloat16(vv[q]);
        __nv_bfloat16 lo = __float2bfloat16(vv[q] - __bfloat162float(hi));
        g_Wxh[i + q] = *(uint16_t*)&hi;
        g_Wxl[i + q] = *(uint16_t*)&lo;
    }
}

// xp cols [0,256) -> bf16 hi/lo (delta_raw operand)
__global__ void __launch_bounds__(256)
split_xp_k() {
    size_t i = ((size_t)blockIdx.x * blockDim.x + threadIdx.x) * 4;   // over 1024*256
    int row = (int)(i >> 8);
    int col = (int)(i & 255);
    float4 v = *(const float4*)(g_xp + (size_t)row * XP_COLS + col);
    float vv[4] = {v.x, v.y, v.z, v.w};
    #pragma unroll
    for (int q = 0; q < 4; q++) {
        __nv_bfloat16 hi = __float2bfloat16(vv[q]);
        __nv_bfloat16 lo = __float2bfloat16(vv[q] - __bfloat162float(hi));
        g_dh[i + q] = *(uint16_t*)&hi;
        g_dl[i + q] = *(uint16_t*)&lo;
    }
}

// ---------------------------------------------------------------------------
// Fused state update. Writes h_new (fp32 output) and ypre split to fp16 hi/lo.
// ---------------------------------------------------------------------------
__global__ void __launch_bounds__(256)
state_update(const float* __restrict__ x,
             const float* __restrict__ h,
             const float* __restrict__ A_log,
             const float* __restrict__ Dv,
             float* __restrict__ h_new)
{
    __shared__ float sA[D_STATE], sB[D_STATE], sC[D_STATE];
    const int b = blockIdx.y;
    const int d = blockIdx.x * blockDim.x + threadIdx.x;

    if (threadIdx.x < D_STATE) {
        int n = threadIdx.x;
        sA[n] = -expf(A_log[n]);
        sB[n] = g_xp[(size_t)b * XP_COLS + DT_RANK + n];
        sC[n] = g_xp[(size_t)b * XP_COLS + DT_RANK + D_STATE + n];
    }
    __syncthreads();

    const size_t bd = (size_t)b * D_MODEL + d;
    const float delta = g_delta[bd];
    const float xv = x[bd];
    const float dx = delta * xv;

    const float4* hp = (const float4*)(h + bd * D_STATE);
    float4* hop = (float4*)(h_new + bd * D_STATE);

    float acc = 0.0f;
    #pragma unroll
    for (int q = 0; q < 4; q++) {
        float4 hv = hp[q];
        float h0 = __expf(delta * sA[4 * q + 0]) * hv.x + dx * sB[4 * q + 0];
        float h1 = __expf(delta * sA[4 * q + 1]) * hv.y + dx * sB[4 * q + 1];
        float h2 = __expf(delta * sA[4 * q + 2]) * hv.z + dx * sB[4 * q + 2];
        float h3 = __expf(delta * sA[4 * q + 3]) * hv.w + dx * sB[4 * q + 3];
        acc += sC[4 * q + 0] * h0 + sC[4 * q + 1] * h1
             + sC[4 * q + 2] * h2 + sC[4 * q + 3] * h3;
        hop[q] = make_float4(h0, h1, h2, h3);
    }
    float ypre = acc + Dv[d] * xv;
    __half hi = __float2half_rn(ypre);
    __half lo = __float2half_rn(ypre - __half2float(hi));
    g_Yh[bd] = *(uint16_t*)&hi;
    g_Yl[bd] = *(uint16_t*)&lo;
}

// ---------------------------------------------------------------------------
// Unified HMMA GEMM: C[m,n] (+)= sum_k A[m,k]*B[n,k], 16-bit operands.
//   A = Ah + Al (2-term split). If BSPLIT: B = Bh + Bl, 3 products
//   (Ah*Bh + Al*Bh + Ah*Bl); else 2 products ((Ah+Al)*Bh).
// CTA 128x128, BK=32, 8 warps (2Mx4N), warp tile 64x32. 80B-padded SMEM rows.
// EPI: 0 = store, 1 = softplus(acc+bias[col]) store, 2 = guarded atomicAdd.
// Split-K via blockIdx.z (k_begin = z*niters*32).
// ---------------------------------------------------------------------------
#define ROW_B 80
#define TILE_B (128 * ROW_B)          // 10240

template<int DT, bool BSPLIT, int EPI, int NSTAGE>
__global__ void __launch_bounds__(256, 1)
gemm16(const uint16_t* __restrict__ Ah, const uint16_t* __restrict__ Al,
       const uint16_t* __restrict__ Bh, const uint16_t* __restrict__ Bl,
       float* __restrict__ C, int ldc, int ldab, int niters,
       const float* __restrict__ bias, int n_real)
{
    constexpr int NTILES = BSPLIT ? 4 : 3;
    constexpr uint32_t OFF_A0 = 0;
    constexpr uint32_t OFF_A1 = TILE_B;
    constexpr uint32_t OFF_B0 = 2 * TILE_B;
    constexpr uint32_t OFF_B1 = 3 * TILE_B;      // only if BSPLIT
    constexpr uint32_t STAGE = NTILES * TILE_B;

    extern __shared__ char smem[];
    const uint32_t sb = smem_u32(smem);
    const int tid = threadIdx.x;
    const int wid = tid >> 5;
    const int lane = tid & 31;
    const int warp_m = wid >> 2;
    const int warp_n = wid & 3;
    const int bm = blockIdx.x * 128;
    const int bn = blockIdx.y * 128;
    const int k_begin = blockIdx.z * niters * 32;

    auto load_stage = [&](uint32_t st, int k0) {
        #pragma unroll
        for (int cc = 0; cc < 2; cc++) {
            const int idx = tid + 256 * cc;
            const int row = idx >> 2;
            const int ch  = idx & 3;
            const uint32_t d = st + (uint32_t)(row * ROW_B + ch * 16);
            const int gk = k0 + ch * 8;
            cpasync16(d + OFF_A0, Ah + (size_t)(bm + row) * ldab + gk);
            cpasync16(d + OFF_A1, Al + (size_t)(bm + row) * ldab + gk);
            cpasync16(d + OFF_B0, Bh + (size_t)(bn + row) * ldab + gk);
            if constexpr (BSPLIT)
                cpasync16(d + OFF_B1, Bl + (size_t)(bn + row) * ldab + gk);
        }
        cpasync_commit();
    };

    // ldmatrix per-lane byte offsets (within a tile, ks=0)
    uint32_t aoff[4], boff[2];
    #pragma unroll
    for (int mi = 0; mi < 4; mi++)
        aoff[mi] = (uint32_t)((warp_m * 64 + mi * 16 + (lane & 15)) * ROW_B + (lane >> 4) * 16);
    #pragma unroll
    for (int pi = 0; pi < 2; pi++) {
        int chunk = lane >> 3;
        int n = warp_n * 32 + pi * 16 + (chunk >> 1) * 8 + (lane & 7);
        boff[pi] = (uint32_t)(n * ROW_B + (chunk & 1) * 16);
    }

    float acc[4][4][4];
    #pragma unroll
    for (int mi = 0; mi < 4; mi++)
        #pragma unroll
        for (int ni = 0; ni < 4; ni++)
            #pragma unroll
            for (int q = 0; q < 4; q++) acc[mi][ni][q] = 0.0f;

    // prologue: stages 0..NSTAGE-2
    #pragma unroll
    for (int s = 0; s < NSTAGE - 1; s++)
        load_stage(sb + s * STAGE, k_begin + s * 32);

    for (int it = 0; it < niters; it++) {
        if (it + NSTAGE - 1 < niters)
            load_stage(sb + ((it + NSTAGE - 1) % NSTAGE) * STAGE,
                       k_begin + (it + NSTAGE - 1) * 32);
        else
            cpasync_commit();   // keep group count uniform
        asm volatile("cp.async.wait_group %0;" :: "n"(NSTAGE - 1) : "memory");
        __syncthreads();

        const uint32_t st = sb + (it % NSTAGE) * STAGE;
        #pragma unroll
        for (int ks = 0; ks < 2; ks++) {
            uint32_t a0[4][4], a1[4][4], b0[2][4], b1[2][4];
            #pragma unroll
            for (int mi = 0; mi < 4; mi++) {
                ldmatrix_x4(a0[mi], st + OFF_A0 + aoff[mi] + ks * 32);
                ldmatrix_x4(a1[mi], st + OFF_A1 + aoff[mi] + ks * 32);
            }
            #pragma unroll
            for (int pi = 0; pi < 2; pi++) {
                ldmatrix_x4(b0[pi], st + OFF_B0 + boff[pi] + ks * 32);
                if constexpr (BSPLIT)
                    ldmatrix_x4(b1[pi], st + OFF_B1 + boff[pi] + ks * 32);
            }
            #pragma unroll
            for (int mi = 0; mi < 4; mi++) {
                #pragma unroll
                for (int ni = 0; ni < 4; ni++) {
                    const int pi = ni >> 1;
                    const int sel = (ni & 1) * 2;
                    uint32_t bh[2] = {b0[pi][sel], b0[pi][sel + 1]};
                    mma16<DT>(acc[mi][ni], a0[mi], bh);
                    mma16<DT>(acc[mi][ni], a1[mi], bh);
                    if constexpr (BSPLIT) {
                        uint32_t bl[2] = {b1[pi][sel], b1[pi][sel + 1]};
                        mma16<DT>(acc[mi][ni], a0[mi], bl);
                    }
                }
            }
        }
        __syncthreads();
    }

    // epilogue
    #pragma unroll
    for (int mi = 0; mi < 4; mi++) {
        const int row = bm + warp_m * 64 + mi * 16 + (lane >> 2);
        #pragma unroll
        for (int ni = 0; ni < 4; ni++) {
            const int col = bn + warp_n * 32 + ni * 8 + (lane & 3) * 2;
            float* acc4 = acc[mi][ni];
            if constexpr (EPI == 0) {
                *(float2*)(C + (size_t)row * ldc + col) = make_float2(acc4[0], acc4[1]);
                *(float2*)(C + (size_t)(row + 8) * ldc + col) = make_float2(acc4[2], acc4[3]);
            } else if constexpr (EPI == 1) {
                float b0v = bias[col], b1v = bias[col + 1];
                *(float2*)(C + (size_t)row * ldc + col) =
                    make_float2(softplusf(acc4[0] + b0v), softplusf(acc4[1] + b1v));
                *(float2*)(C + (size_t)(row + 8) * ldc + col) =
                    make_float2(softplusf(acc4[2] + b0v), softplusf(acc4[3] + b1v));
            } else {
                if (col < n_real) {   // col even, n_real even -> covers col+1
                    atomicAdd(&C[(size_t)row * ldc + col],       acc4[0]);
                    atomicAdd(&C[(size_t)row * ldc + col + 1],   acc4[1]);
                    atomicAdd(&C[(size_t)(row + 8) * ldc + col],     acc4[2]);
                    atomicAdd(&C[(size_t)(row + 8) * ldc + col + 1], acc4[3]);
                }
            }
        }
    }
}

// ---------------------------------------------------------------------------
// Launch. Inputs: x, h, W_xproj, W_dt, b_dt, A_log, D, W_out.
// Output: [y (1024*4096), h_new (1024*4096*16)].
// ---------------------------------------------------------------------------
extern "C" void kernel_launch(void* const* d_in, const int* in_sizes, int n_in,
                              void* d_out, int out_size)
{
    const float* x    = (const float*)d_in[0];
    const float* h    = (const float*)d_in[1];
    const float* Wxp  = (const float*)d_in[2];
    const float* Wdt  = (const float*)d_in[3];
    const float* bdt  = (const float*)d_in[4];
    const float* Alog = (const float*)d_in[5];
    const float* Dv   = (const float*)d_in[6];
    const float* Wout = (const float*)d_in[7];

    float* y_out    = (float*)d_out;
    float* hnew_out = y_out + (size_t)BATCH * D_MODEL;

    float *xp_p, *delta_p;
    uint16_t *Wh16_p, *Yh_p, *Yl_p, *xh_p, *xl_p, *Wxh_p, *Wxl_p, *dh_p, *dl_p, *Wdh_p, *Wdl_p;
    cudaGetSymbolAddress((void**)&xp_p, g_xp);
    cudaGetSymbolAddress((void**)&delta_p, g_delta);
    cudaGetSymbolAddress((void**)&Wh16_p, g_Wh16);
    cudaGetSymbolAddress((void**)&Yh_p, g_Yh);
    cudaGetSymbolAddress((void**)&Yl_p, g_Yl);
    cudaGetSymbolAddress((void**)&xh_p, g_xh);
    cudaGetSymbolAddress((void**)&xl_p, g_xl);
    cudaGetSymbolAddress((void**)&Wxh_p, g_Wxh);
    cudaGetSymbolAddress((void**)&Wxl_p, g_Wxl);
    cudaGetSymbolAddress((void**)&dh_p, g_dh);
    cudaGetSymbolAddress((void**)&dl_p, g_dl);
    cudaGetSymbolAddress((void**)&Wdh_p, g_Wdh);
    cudaGetSymbolAddress((void**)&Wdl_p, g_Wdl);

    const int SMEM4 = 2 * 4 * TILE_B;   // 81920  (bf16x3, 2 stages)
    const int SMEM3 = 3 * 3 * TILE_B;   // 92160  (fp16x2, 3 stages)
    cudaFuncSetAttribute((const void*)gemm16<0, true, 2, 2>,
                         cudaFuncAttributeMaxDynamicSharedMemorySize, SMEM4);
    cudaFuncSetAttribute((const void*)gemm16<0, true, 1, 2>,
                         cudaFuncAttributeMaxDynamicSharedMemorySize, SMEM4);
    cudaFuncSetAttribute((const void*)gemm16<1, false, 0, 3>,
                         cudaFuncAttributeMaxDynamicSharedMemorySize, SMEM3);

    // Operand preparation
    conv_fp16_k<<<(D_MODEL * D_MODEL) / (4 * 256), 256>>>(Wout, Wh16_p);
    split_bf16_k<<<(BATCH * D_MODEL) / (4 * 256), 256>>>(x, xh_p, xl_p);
    split_wxproj_k<<<(WXP_PAD * D_MODEL) / (4 * 256), 256>>>(Wxp);
    split_bf16_k<<<(D_MODEL * DT_RANK) / (4 * 256), 256>>>(Wdt, Wdh_p, Wdl_p);
    zero_xp_kernel<<<(BATCH * XP_COLS + 255) / 256, 256>>>();

    // G1: xp = x @ W_xproj^T  (bf16x3 HMMA, split-K=8, guarded atomic epilogue)
    gemm16<0, true, 2, 2><<<dim3(BATCH / 128, WXP_PAD / 128, 8), 256, SMEM4>>>(
        xh_p, xl_p, Wxh_p, Wxl_p, xp_p, XP_COLS, D_MODEL, (D_MODEL / 8) / 32,
        nullptr, XP_COLS);

    // delta_raw split (xp cols 0..255 -> bf16 hi/lo)
    split_xp_k<<<(BATCH * DT_RANK) / (4 * 256), 256>>>();

    // G2: delta = softplus(delta_raw @ W_dt^T + b_dt)  (bf16x3 HMMA)
    gemm16<0, true, 1, 2><<<dim3(BATCH / 128, D_MODEL / 128, 1), 256, SMEM4>>>(
        dh_p, dl_p, Wdh_p, Wdl_p, delta_p, D_MODEL, DT_RANK, DT_RANK / 32,
        bdt, D_MODEL);

    // S: state update; h_new out + ypre -> fp16 hi/lo
    state_update<<<dim3(D_MODEL / 256, BATCH), 256>>>(x, h, Alog, Dv, hnew_out);

    // G3: y = ypre @ W_out^T  (fp16 2-product HMMA, 3-stage pipeline)
    gemm16<1, false, 0, 3><<<dim3(BATCH / 128, D_MODEL / 128, 1), 256, SMEM3>>>(
        Yh_p, Yl_p, Wh16_p, nullptr, y_out, D_MODEL, D_MODEL, D_MODEL / 32,
        nullptr, D_MODEL);
}

// round 6
// speedup vs baseline: 3.1614x; 1.2419x over previous
#include <cuda_runtime.h>
#include <cuda_bf16.h>
#include <cuda_fp16.h>
#include <math.h>
#include <stdint.h>

#define BATCH   1024
#define D_MODEL 4096
#define D_STATE 16
#define DT_RANK 256
#define XP_COLS (DT_RANK + 2 * D_STATE)   // 288
#define WXP_PAD 384                        // 288 padded to 3 x 128

// ---------------- scratch (allocation-free rule: __device__ globals) --------
__device__ float g_xp[BATCH * XP_COLS];
__device__ float g_delta[BATCH * D_MODEL];
__device__ uint16_t g_Wh16[(size_t)D_MODEL * D_MODEL];   // fp16(W_out)
__device__ uint16_t g_Yh[(size_t)BATCH * D_MODEL];       // fp16(ypre)
__device__ uint16_t g_xh[(size_t)BATCH * D_MODEL];       // bf16 hi(x)
__device__ uint16_t g_xl[(size_t)BATCH * D_MODEL];       // bf16 lo(x)
__device__ uint16_t g_Wxh[(size_t)WXP_PAD * D_MODEL];    // bf16 hi(W_xproj), padded
__device__ uint16_t g_Wxl[(size_t)WXP_PAD * D_MODEL];
__device__ uint16_t g_dh[(size_t)BATCH * DT_RANK];       // bf16 hi(delta_raw)
__device__ uint16_t g_dl[(size_t)BATCH * DT_RANK];
__device__ uint16_t g_Wdh[(size_t)D_MODEL * DT_RANK];    // bf16 hi(W_dt)
__device__ uint16_t g_Wdl[(size_t)D_MODEL * DT_RANK];

__device__ __forceinline__ float softplusf(float z) {
    return (z > 20.0f) ? z : log1pf(__expf(z));
}

// ---------------- PTX helpers (sm_80-class only; no 'a'-target features) ----
__device__ __forceinline__ uint32_t smem_u32(const void* p) {
    uint32_t a;
    asm("{ .reg .u64 t; cvta.to.shared.u64 t, %1; cvt.u32.u64 %0, t; }" : "=r"(a) : "l"(p));
    return a;
}
__device__ __forceinline__ void cpasync16(uint32_t dst, const void* src) {
    asm volatile("cp.async.cg.shared.global [%0], [%1], 16;" :: "r"(dst), "l"(src));
}
__device__ __forceinline__ void cpasync_commit() {
    asm volatile("cp.async.commit_group;" ::: "memory");
}
__device__ __forceinline__ void ldmatrix_x4(uint32_t* r, uint32_t addr) {
    asm volatile("ldmatrix.sync.aligned.m8n8.x4.shared.b16 {%0,%1,%2,%3}, [%4];"
                 : "=r"(r[0]), "=r"(r[1]), "=r"(r[2]), "=r"(r[3]) : "r"(addr));
}
// DT: 0 = bf16, 1 = fp16
template<int DT>
__device__ __forceinline__ void mma16(float* c, const uint32_t* a, const uint32_t* b) {
    if constexpr (DT == 0) {
        asm volatile(
            "mma.sync.aligned.m16n8k16.row.col.f32.bf16.bf16.f32 "
            "{%0,%1,%2,%3}, {%4,%5,%6,%7}, {%8,%9}, {%0,%1,%2,%3};"
            : "+f"(c[0]), "+f"(c[1]), "+f"(c[2]), "+f"(c[3])
            : "r"(a[0]), "r"(a[1]), "r"(a[2]), "r"(a[3]), "r"(b[0]), "r"(b[1]));
    } else {
        asm volatile(
            "mma.sync.aligned.m16n8k16.row.col.f32.f16.f16.f32 "
            "{%0,%1,%2,%3}, {%4,%5,%6,%7}, {%8,%9}, {%0,%1,%2,%3};"
            : "+f"(c[0]), "+f"(c[1]), "+f"(c[2]), "+f"(c[3])
            : "r"(a[0]), "r"(a[1]), "r"(a[2]), "r"(a[3]), "r"(b[0]), "r"(b[1]));
    }
}

// ---------------------------------------------------------------------------
// Conversion / split kernels
// ---------------------------------------------------------------------------
__global__ void zero_xp_kernel() {
    int i = blockIdx.x * blockDim.x + threadIdx.x;
    if (i < BATCH * XP_COLS) g_xp[i] = 0.0f;
}

// fp32 -> bf16 hi/lo (exact grid, 4 elems/thread)
__global__ void __launch_bounds__(256)
split_bf16_k(const float* __restrict__ in, uint16_t* __restrict__ h, uint16_t* __restrict__ l) {
    size_t i = ((size_t)blockIdx.x * blockDim.x + threadIdx.x) * 4;
    float4 v = *(const float4*)(in + i);
    float vv[4] = {v.x, v.y, v.z, v.w};
    #pragma unroll
    for (int q = 0; q < 4; q++) {
        __nv_bfloat16 hi = __float2bfloat16(vv[q]);
        __nv_bfloat16 lo = __float2bfloat16(vv[q] - __bfloat162float(hi));
        h[i + q] = *(uint16_t*)&hi;
        l[i + q] = *(uint16_t*)&lo;
    }
}

// fp32 -> fp16 single (W_out)
__global__ void __launch_bounds__(256)
conv_fp16_k(const float* __restrict__ in, uint16_t* __restrict__ out) {
    size_t i = ((size_t)blockIdx.x * blockDim.x + threadIdx.x) * 4;
    float4 v = *(const float4*)(in + i);
    __half h0 = __float2half_rn(v.x), h1 = __float2half_rn(v.y);
    __half h2 = __float2half_rn(v.z), h3 = __float2half_rn(v.w);
    uint16_t* o = out + i;
    o[0] = *(uint16_t*)&h0; o[1] = *(uint16_t*)&h1;
    o[2] = *(uint16_t*)&h2; o[3] = *(uint16_t*)&h3;
}

// W_xproj (288x4096) -> bf16 hi/lo padded to 384 rows (zeros beyond 288)
__global__ void __launch_bounds__(256)
split_wxproj_k(const float* __restrict__ in) {
    size_t i = ((size_t)blockIdx.x * blockDim.x + threadIdx.x) * 4;   // over 384*4096
    int row = (int)(i >> 12);
    float vv[4] = {0.f, 0.f, 0.f, 0.f};
    if (row < XP_COLS) {
        float4 v = *(const float4*)(in + i);
        vv[0] = v.x; vv[1] = v.y; vv[2] = v.z; vv[3] = v.w;
    }
    #pragma unroll
    for (int q = 0; q < 4; q++) {
        __nv_bfloat16 hi = __float2bfloat16(vv[q]);
        __nv_bfloat16 lo = __float2bfloat16(vv[q] - __bfloat162float(hi));
        g_Wxh[i + q] = *(uint16_t*)&hi;
        g_Wxl[i + q] = *(uint16_t*)&lo;
    }
}

// xp cols [0,256) -> bf16 hi/lo (delta_raw operand)
__global__ void __launch_bounds__(256)
split_xp_k() {
    size_t i = ((size_t)blockIdx.x * blockDim.x + threadIdx.x) * 4;   // over 1024*256
    int row = (int)(i >> 8);
    int col = (int)(i & 255);
    float4 v = *(const float4*)(g_xp + (size_t)row * XP_COLS + col);
    float vv[4] = {v.x, v.y, v.z, v.w};
    #pragma unroll
    for (int q = 0; q < 4; q++) {
        __nv_bfloat16 hi = __float2bfloat16(vv[q]);
        __nv_bfloat16 lo = __float2bfloat16(vv[q] - __bfloat162float(hi));
        g_dh[i + q] = *(uint16_t*)&hi;
        g_dl[i + q] = *(uint16_t*)&lo;
    }
}

// ---------------------------------------------------------------------------
// Fused state update. Writes h_new (fp32 output) and ypre -> fp16.
// ---------------------------------------------------------------------------
__global__ void __launch_bounds__(256)
state_update(const float* __restrict__ x,
             const float* __restrict__ h,
             const float* __restrict__ A_log,
             const float* __restrict__ Dv,
             float* __restrict__ h_new)
{
    __shared__ float sA[D_STATE], sB[D_STATE], sC[D_STATE];
    const int b = blockIdx.y;
    const int d = blockIdx.x * blockDim.x + threadIdx.x;

    if (threadIdx.x < D_STATE) {
        int n = threadIdx.x;
        sA[n] = -expf(A_log[n]);
        sB[n] = g_xp[(size_t)b * XP_COLS + DT_RANK + n];
        sC[n] = g_xp[(size_t)b * XP_COLS + DT_RANK + D_STATE + n];
    }
    __syncthreads();

    const size_t bd = (size_t)b * D_MODEL + d;
    const float delta = g_delta[bd];
    const float xv = x[bd];
    const float dx = delta * xv;

    const float4* hp = (const float4*)(h + bd * D_STATE);
    float4* hop = (float4*)(h_new + bd * D_STATE);

    float acc = 0.0f;
    #pragma unroll
    for (int q = 0; q < 4; q++) {
        float4 hv = hp[q];
        float h0 = __expf(delta * sA[4 * q + 0]) * hv.x + dx * sB[4 * q + 0];
        float h1 = __expf(delta * sA[4 * q + 1]) * hv.y + dx * sB[4 * q + 1];
        float h2 = __expf(delta * sA[4 * q + 2]) * hv.z + dx * sB[4 * q + 2];
        float h3 = __expf(delta * sA[4 * q + 3]) * hv.w + dx * sB[4 * q + 3];
        acc += sC[4 * q + 0] * h0 + sC[4 * q + 1] * h1
             + sC[4 * q + 2] * h2 + sC[4 * q + 3] * h3;
        hop[q] = make_float4(h0, h1, h2, h3);
    }
    float ypre = acc + Dv[d] * xv;
    __half hi = __float2half_rn(ypre);
    g_Yh[bd] = *(uint16_t*)&hi;
}

// ---------------------------------------------------------------------------
// Unified HMMA GEMM: C[m,n] (+)= sum_k A[m,k]*B[n,k], 16-bit operands.
//   ASPLIT: A = Ah + Al. BSPLIT: adds Ah*Bl cross term (requires ASPLIT).
//   Products: 1 (no split), 2 (ASPLIT), 3 (ASPLIT+BSPLIT).
// CTA 128x128, BK=32, 8 warps (2Mx4N), warp tile 64x32. 80B-padded SMEM rows.
// EPI: 0 = store, 1 = softplus(acc+bias[col]) store, 2 = guarded atomicAdd.
// Split-K via blockIdx.z (k_begin = z*niters*32).
// ---------------------------------------------------------------------------
#define ROW_B 80
#define TILE_B (128 * ROW_B)          // 10240

template<int DT, bool ASPLIT, bool BSPLIT, int EPI, int NSTAGE>
__global__ void __launch_bounds__(256, 1)
gemm16(const uint16_t* __restrict__ Ah, const uint16_t* __restrict__ Al,
       const uint16_t* __restrict__ Bh, const uint16_t* __restrict__ Bl,
       float* __restrict__ C, int ldc, int ldab, int niters,
       const float* __restrict__ bias, int n_real)
{
    constexpr int NTILES = 1 + (ASPLIT ? 1 : 0) + 1 + (BSPLIT ? 1 : 0);
    constexpr uint32_t OFF_A0 = 0;
    constexpr uint32_t OFF_A1 = ASPLIT ? TILE_B : 0;
    constexpr uint32_t OFF_B0 = (ASPLIT ? 2 : 1) * TILE_B;
    constexpr uint32_t OFF_B1 = (ASPLIT ? 3 : 2) * TILE_B;   // only if BSPLIT
    constexpr uint32_t STAGE = NTILES * TILE_B;

    extern __shared__ char smem[];
    const uint32_t sb = smem_u32(smem);
    const int tid = threadIdx.x;
    const int wid = tid >> 5;
    const int lane = tid & 31;
    const int warp_m = wid >> 2;
    const int warp_n = wid & 3;
    const int bm = blockIdx.x * 128;
    const int bn = blockIdx.y * 128;
    const int k_begin = blockIdx.z * niters * 32;

    auto load_stage = [&](uint32_t st, int k0) {
        #pragma unroll
        for (int cc = 0; cc < 2; cc++) {
            const int idx = tid + 256 * cc;
            const int row = idx >> 2;
            const int ch  = idx & 3;
            const uint32_t d = st + (uint32_t)(row * ROW_B + ch * 16);
            const int gk = k0 + ch * 8;
            cpasync16(d + OFF_A0, Ah + (size_t)(bm + row) * ldab + gk);
            if constexpr (ASPLIT)
                cpasync16(d + OFF_A1, Al + (size_t)(bm + row) * ldab + gk);
            cpasync16(d + OFF_B0, Bh + (size_t)(bn + row) * ldab + gk);
            if constexpr (BSPLIT)
                cpasync16(d + OFF_B1, Bl + (size_t)(bn + row) * ldab + gk);
        }
        cpasync_commit();
    };

    // ldmatrix per-lane byte offsets (within a tile, ks=0)
    uint32_t aoff[4], boff[2];
    #pragma unroll
    for (int mi = 0; mi < 4; mi++)
        aoff[mi] = (uint32_t)((warp_m * 64 + mi * 16 + (lane & 15)) * ROW_B + (lane >> 4) * 16);
    #pragma unroll
    for (int pi = 0; pi < 2; pi++) {
        int chunk = lane >> 3;
        int n = warp_n * 32 + pi * 16 + (chunk >> 1) * 8 + (lane & 7);
        boff[pi] = (uint32_t)(n * ROW_B + (chunk & 1) * 16);
    }

    float acc[4][4][4];
    #pragma unroll
    for (int mi = 0; mi < 4; mi++)
        #pragma unroll
        for (int ni = 0; ni < 4; ni++)
            #pragma unroll
            for (int q = 0; q < 4; q++) acc[mi][ni][q] = 0.0f;

    // prologue: stages 0..NSTAGE-2
    #pragma unroll
    for (int s = 0; s < NSTAGE - 1; s++)
        load_stage(sb + s * STAGE, k_begin + s * 32);

    for (int it = 0; it < niters; it++) {
        if (it + NSTAGE - 1 < niters)
            load_stage(sb + ((it + NSTAGE - 1) % NSTAGE) * STAGE,
                       k_begin + (it + NSTAGE - 1) * 32);
        else
            cpasync_commit();   // keep group count uniform
        asm volatile("cp.async.wait_group %0;" :: "n"(NSTAGE - 1) : "memory");
        __syncthreads();

        const uint32_t st = sb + (it % NSTAGE) * STAGE;
        #pragma unroll
        for (int ks = 0; ks < 2; ks++) {
            uint32_t a0[4][4], a1[4][4], b0[2][4], b1[2][4];
            #pragma unroll
            for (int mi = 0; mi < 4; mi++) {
                ldmatrix_x4(a0[mi], st + OFF_A0 + aoff[mi] + ks * 32);
                if constexpr (ASPLIT)
                    ldmatrix_x4(a1[mi], st + OFF_A1 + aoff[mi] + ks * 32);
            }
            #pragma unroll
            for (int pi = 0; pi < 2; pi++) {
                ldmatrix_x4(b0[pi], st + OFF_B0 + boff[pi] + ks * 32);
                if constexpr (BSPLIT)
                    ldmatrix_x4(b1[pi], st + OFF_B1 + boff[pi] + ks * 32);
            }
            #pragma unroll
            for (int mi = 0; mi < 4; mi++) {
                #pragma unroll
                for (int ni = 0; ni < 4; ni++) {
                    const int pi = ni >> 1;
                    const int sel = (ni & 1) * 2;
                    uint32_t bh[2] = {b0[pi][sel], b0[pi][sel + 1]};
                    mma16<DT>(acc[mi][ni], a0[mi], bh);
                    if constexpr (ASPLIT)
                        mma16<DT>(acc[mi][ni], a1[mi], bh);
                    if constexpr (BSPLIT) {
                        uint32_t bl[2] = {b1[pi][sel], b1[pi][sel + 1]};
                        mma16<DT>(acc[mi][ni], a0[mi], bl);
                    }
                }
            }
        }
        __syncthreads();
    }

    // epilogue
    #pragma unroll
    for (int mi = 0; mi < 4; mi++) {
        const int row = bm + warp_m * 64 + mi * 16 + (lane >> 2);
        #pragma unroll
        for (int ni = 0; ni < 4; ni++) {
            const int col = bn + warp_n * 32 + ni * 8 + (lane & 3) * 2;
            float* acc4 = acc[mi][ni];
            if constexpr (EPI == 0) {
                *(float2*)(C + (size_t)row * ldc + col) = make_float2(acc4[0], acc4[1]);
                *(float2*)(C + (size_t)(row + 8) * ldc + col) = make_float2(acc4[2], acc4[3]);
            } else if constexpr (EPI == 1) {
                float b0v = bias[col], b1v = bias[col + 1];
                *(float2*)(C + (size_t)row * ldc + col) =
                    make_float2(softplusf(acc4[0] + b0v), softplusf(acc4[1] + b1v));
                *(float2*)(C + (size_t)(row + 8) * ldc + col) =
                    make_float2(softplusf(acc4[2] + b0v), softplusf(acc4[3] + b1v));
            } else {
                if (col < n_real) {   // col even, n_real even -> covers col+1
                    atomicAdd(&C[(size_t)row * ldc + col],       acc4[0]);
                    atomicAdd(&C[(size_t)row * ldc + col + 1],   acc4[1]);
                    atomicAdd(&C[(size_t)(row + 8) * ldc + col],     acc4[2]);
                    atomicAdd(&C[(size_t)(row + 8) * ldc + col + 1], acc4[3]);
                }
            }
        }
    }
}

// ---------------------------------------------------------------------------
// Launch. Inputs: x, h, W_xproj, W_dt, b_dt, A_log, D, W_out.
// Output: [y (1024*4096), h_new (1024*4096*16)].
// ---------------------------------------------------------------------------
extern "C" void kernel_launch(void* const* d_in, const int* in_sizes, int n_in,
                              void* d_out, int out_size)
{
    const float* x    = (const float*)d_in[0];
    const float* h    = (const float*)d_in[1];
    const float* Wxp  = (const float*)d_in[2];
    const float* Wdt  = (const float*)d_in[3];
    const float* bdt  = (const float*)d_in[4];
    const float* Alog = (const float*)d_in[5];
    const float* Dv   = (const float*)d_in[6];
    const float* Wout = (const float*)d_in[7];

    float* y_out    = (float*)d_out;
    float* hnew_out = y_out + (size_t)BATCH * D_MODEL;

    float *xp_p, *delta_p;
    uint16_t *Wh16_p, *Yh_p, *xh_p, *xl_p, *Wxh_p, *Wxl_p, *dh_p, *dl_p, *Wdh_p, *Wdl_p;
    cudaGetSymbolAddress((void**)&xp_p, g_xp);
    cudaGetSymbolAddress((void**)&delta_p, g_delta);
    cudaGetSymbolAddress((void**)&Wh16_p, g_Wh16);
    cudaGetSymbolAddress((void**)&Yh_p, g_Yh);
    cudaGetSymbolAddress((void**)&xh_p, g_xh);
    cudaGetSymbolAddress((void**)&xl_p, g_xl);
    cudaGetSymbolAddress((void**)&Wxh_p, g_Wxh);
    cudaGetSymbolAddress((void**)&Wxl_p, g_Wxl);
    cudaGetSymbolAddress((void**)&dh_p, g_dh);
    cudaGetSymbolAddress((void**)&dl_p, g_dl);
    cudaGetSymbolAddress((void**)&Wdh_p, g_Wdh);
    cudaGetSymbolAddress((void**)&Wdl_p, g_Wdl);

    const int SMEM4 = 2 * 4 * TILE_B;   // 81920  (bf16x3: 4 tiles, 2 stages)
    const int SMEM2 = 4 * 2 * TILE_B;   // 81920  (fp16x1: 2 tiles, 4 stages)
    cudaFuncSetAttribute((const void*)gemm16<0, true, true, 2, 2>,
                         cudaFuncAttributeMaxDynamicSharedMemorySize, SMEM4);
    cudaFuncSetAttribute((const void*)gemm16<0, true, true, 1, 2>,
                         cudaFuncAttributeMaxDynamicSharedMemorySize, SMEM4);
    cudaFuncSetAttribute((const void*)gemm16<1, false, false, 0, 4>,
                         cudaFuncAttributeMaxDynamicSharedMemorySize, SMEM2);

    // Operand preparation
    conv_fp16_k<<<(D_MODEL * D_MODEL) / (4 * 256), 256>>>(Wout, Wh16_p);
    split_bf16_k<<<(BATCH * D_MODEL) / (4 * 256), 256>>>(x, xh_p, xl_p);
    split_wxproj_k<<<(WXP_PAD * D_MODEL) / (4 * 256), 256>>>(Wxp);
    split_bf16_k<<<(D_MODEL * DT_RANK) / (4 * 256), 256>>>(Wdt, Wdh_p, Wdl_p);
    zero_xp_kernel<<<(BATCH * XP_COLS + 255) / 256, 256>>>();

    // G1: xp = x @ W_xproj^T  (bf16x3 HMMA, split-K=8, guarded atomic epilogue)
    gemm16<0, true, true, 2, 2><<<dim3(BATCH / 128, WXP_PAD / 128, 8), 256, SMEM4>>>(
        xh_p, xl_p, Wxh_p, Wxl_p, xp_p, XP_COLS, D_MODEL, (D_MODEL / 8) / 32,
        nullptr, XP_COLS);

    // delta_raw split (xp cols 0..255 -> bf16 hi/lo)
    split_xp_k<<<(BATCH * DT_RANK) / (4 * 256), 256>>>();

    // G2: delta = softplus(delta_raw @ W_dt^T + b_dt)  (bf16x3 HMMA)
    gemm16<0, true, true, 1, 2><<<dim3(BATCH / 128, D_MODEL / 128, 1), 256, SMEM4>>>(
        dh_p, dl_p, Wdh_p, Wdl_p, delta_p, D_MODEL, DT_RANK, DT_RANK / 32,
        bdt, D_MODEL);

    // S: state update; h_new out + ypre -> fp16
    state_update<<<dim3(D_MODEL / 256, BATCH), 256>>>(x, h, Alog, Dv, hnew_out);

    // G3: y = fp16(ypre) @ fp16(W_out)^T  (single product, 4-stage pipeline)
    gemm16<1, false, false, 0, 4><<<dim3(BATCH / 128, D_MODEL / 128, 1), 256, SMEM2>>>(
        Yh_p, nullptr, Wh16_p, nullptr, y_out, D_MODEL, D_MODEL, D_MODEL / 32,
        nullptr, D_MODEL);
}